// round 1
// baseline (speedup 1.0000x reference)
#include <cuda_runtime.h>

#define BATCH 2
#define CCH   512
#define SSP   2304
#define NH    8
#define HD    64
#define NG    32
#define CPG   16
#define EPSV  1e-5f

// Scratch (allocation-free rule: __device__ globals)
__device__ float g_norm[BATCH * CCH * SSP];        // 9.4 MB
__device__ float g_qkv [BATCH * 3 * CCH * SSP];    // 28.3 MB
__device__ float g_att [BATCH * CCH * SSP];        // 9.4 MB

// ---------------------------------------------------------------------------
// GroupNorm: one block per (batch, group). 16 ch x 2304 = 36864 floats/group.
// ---------------------------------------------------------------------------
__global__ void gn_kernel(const float* __restrict__ x,
                          const float* __restrict__ gamma,
                          const float* __restrict__ beta) {
    int b = blockIdx.x >> 5;
    int g = blockIdx.x & 31;
    const float4* xp = (const float4*)(x + (size_t)(b * CCH + g * CPG) * SSP);
    float4* op = (float4*)(g_norm + (size_t)(b * CCH + g * CPG) * SSP);
    int tid = threadIdx.x;
    const int n4 = CPG * SSP / 4;  // 9216

    float s0 = 0.f, s1 = 0.f;
    for (int i = tid; i < n4; i += 256) {
        float4 v = xp[i];
        s0 += v.x + v.y + v.z + v.w;
        s1 += v.x * v.x + v.y * v.y + v.z * v.z + v.w * v.w;
    }
#pragma unroll
    for (int o = 16; o > 0; o >>= 1) {
        s0 += __shfl_xor_sync(0xffffffffu, s0, o);
        s1 += __shfl_xor_sync(0xffffffffu, s1, o);
    }
    __shared__ float sm0[8], sm1[8];
    __shared__ float stat[2];
    int w = tid >> 5;
    if ((tid & 31) == 0) { sm0[w] = s0; sm1[w] = s1; }
    __syncthreads();
    if (tid == 0) {
        float a = 0.f, q = 0.f;
#pragma unroll
        for (int i = 0; i < 8; i++) { a += sm0[i]; q += sm1[i]; }
        float mean = a * (1.f / 36864.f);
        float var  = q * (1.f / 36864.f) - mean * mean;
        stat[0] = mean;
        stat[1] = rsqrtf(var + EPSV);
    }
    __syncthreads();
    float mean = stat[0], rstd = stat[1];
    for (int i = tid; i < n4; i += 256) {
        int c = g * CPG + i / 576;  // 576 = SSP/4, float4 never crosses channel
        float ga = gamma[c] * rstd;
        float be = beta[c] - mean * ga;
        float4 v = xp[i];
        v.x = v.x * ga + be; v.y = v.y * ga + be;
        v.z = v.z * ga + be; v.w = v.w * ga + be;
        op[i] = v;
    }
}

// ---------------------------------------------------------------------------
// SGEMM: C[M,N] = A[M,K] @ B[K,N] (+bias[M] +res[M,N]).
// 128x128 block tile, K-tile 8, 256 threads, 8x8 microtile (split 4+4 to keep
// LDS.128 conflict-free), register-prefetched global loads.
// ---------------------------------------------------------------------------
__device__ __forceinline__ void sgemm128(
    int M, int N, int K,
    const float* __restrict__ A,
    const float* __restrict__ Bp,
    float* __restrict__ Cp,
    const float* __restrict__ bias,
    const float* __restrict__ res) {
    __shared__ float As[8 * 128];
    __shared__ float Bs[8 * 128];
    int tid = threadIdx.x;
    int tx = tid & 15, ty = tid >> 4;
    int m0 = blockIdx.y * 128, n0 = blockIdx.x * 128;

    int arow = tid >> 1, akq = (tid & 1) * 4;      // A: [128 rows][8 k], f4 along k
    int brow = tid >> 5, bcol = (tid & 31) * 4;    // B: [8 k][128 n], f4 along n
    const float* Aptr = A + (size_t)(m0 + arow) * K + akq;
    const float* Bptr = Bp + (size_t)brow * N + n0 + bcol;

    float4 ra = *(const float4*)Aptr;
    float4 rb = *(const float4*)Bptr;

    float acc[8][8];
#pragma unroll
    for (int i = 0; i < 8; i++)
#pragma unroll
        for (int j = 0; j < 8; j++) acc[i][j] = 0.f;

    int nkt = K >> 3;
    for (int kt = 0; kt < nkt; kt++) {
        As[(akq + 0) * 128 + arow] = ra.x;
        As[(akq + 1) * 128 + arow] = ra.y;
        As[(akq + 2) * 128 + arow] = ra.z;
        As[(akq + 3) * 128 + arow] = ra.w;
        *(float4*)(Bs + brow * 128 + bcol) = rb;
        __syncthreads();
        if (kt + 1 < nkt) {
            ra = *(const float4*)(Aptr + (kt + 1) * 8);
            rb = *(const float4*)(Bptr + (size_t)(kt + 1) * 8 * N);
        }
#pragma unroll
        for (int kk = 0; kk < 8; kk++) {
            float a_[8], b_[8];
            *(float4*)&a_[0] = *(float4*)(As + kk * 128 + 4 * ty);
            *(float4*)&a_[4] = *(float4*)(As + kk * 128 + 64 + 4 * ty);
            *(float4*)&b_[0] = *(float4*)(Bs + kk * 128 + 4 * tx);
            *(float4*)&b_[4] = *(float4*)(Bs + kk * 128 + 64 + 4 * tx);
#pragma unroll
            for (int i = 0; i < 8; i++)
#pragma unroll
                for (int j = 0; j < 8; j++) acc[i][j] += a_[i] * b_[j];
        }
        __syncthreads();
    }

#pragma unroll
    for (int ih = 0; ih < 2; ih++) {
#pragma unroll
        for (int ii = 0; ii < 4; ii++) {
            int m = m0 + ih * 64 + 4 * ty + ii;
            float bv = bias ? bias[m] : 0.f;
#pragma unroll
            for (int jh = 0; jh < 2; jh++) {
                int n = n0 + jh * 64 + 4 * tx;
                float4 o;
                o.x = acc[ih * 4 + ii][jh * 4 + 0] + bv;
                o.y = acc[ih * 4 + ii][jh * 4 + 1] + bv;
                o.z = acc[ih * 4 + ii][jh * 4 + 2] + bv;
                o.w = acc[ih * 4 + ii][jh * 4 + 3] + bv;
                if (res) {
                    float4 r = *(const float4*)(res + (size_t)m * N + n);
                    o.x += r.x; o.y += r.y; o.z += r.z; o.w += r.w;
                }
                *(float4*)(Cp + (size_t)m * N + n) = o;
            }
        }
    }
}

__global__ void __launch_bounds__(256) qkv_gemm_kernel(const float* __restrict__ w_qkv) {
    int b = blockIdx.z;
    sgemm128(3 * CCH, SSP, CCH, w_qkv,
             g_norm + (size_t)b * CCH * SSP,
             g_qkv + (size_t)b * 3 * CCH * SSP,
             nullptr, nullptr);
}

__global__ void __launch_bounds__(256) out_gemm_kernel(const float* __restrict__ w_out,
                                                       const float* __restrict__ b_out,
                                                       const float* __restrict__ x,
                                                       float* __restrict__ out) {
    int b = blockIdx.z;
    sgemm128(CCH, SSP, CCH, w_out,
             g_att + (size_t)b * CCH * SSP,
             out + (size_t)b * CCH * SSP,
             b_out, x + (size_t)b * CCH * SSP);
}

// ---------------------------------------------------------------------------
// Flash attention, fp32. Block = 64 queries of one (b,h). 256 threads (16x16),
// 4x4 microtiles. Online softmax with width-16 shuffle row reductions.
// SMEM: Qs[d][i], KVs (K as [d][j], then V transposed+XOR-swizzled [j][d]),
// Ps[i][j]. 3 x 16KB = exactly 48KB static.
// ---------------------------------------------------------------------------
__global__ void __launch_bounds__(256) attn_kernel() {
    __shared__ float Qs[64 * 64];
    __shared__ float KVs[64 * 64];
    __shared__ float Ps[64 * 64];
    int tid = threadIdx.x;
    int tx = tid & 15, ty = tid >> 4;
    int qt = blockIdx.x, h = blockIdx.y, b = blockIdx.z;
    const float* base = g_qkv + ((size_t)b * 3 * CCH + h * 3 * HD) * SSP;
    const float* qp = base;
    const float* kp = base + (size_t)HD * SSP;
    const float* vp = base + (size_t)2 * HD * SSP;
    int q0 = qt * 64;

    // Load Q tile [d=64][i=64], coalesced along i.
#pragma unroll
    for (int r = 0; r < 4; r++) {
        int f = tid + 256 * r;
        int d = f >> 4, i4 = f & 15;
        *(float4*)(Qs + d * 64 + 4 * i4) =
            *(const float4*)(qp + (size_t)d * SSP + q0 + 4 * i4);
    }

    float m_run[4], l_run[4], acc[4][4];
#pragma unroll
    for (int i = 0; i < 4; i++) {
        m_run[i] = -1e30f; l_run[i] = 0.f;
#pragma unroll
        for (int j = 0; j < 4; j++) acc[i][j] = 0.f;
    }
    const float scale = 0.044194173824159216f;  // 1/sqrt(512)

    for (int t = 0; t < SSP / 64; t++) {
        int t0 = t * 64;
        __syncthreads();  // prev-iter Ps/Vt reads done; Q visible for t=0
        // Load K tile [d][j]
#pragma unroll
        for (int r = 0; r < 4; r++) {
            int f = tid + 256 * r;
            int d = f >> 4, j4 = f & 15;
            *(float4*)(KVs + d * 64 + 4 * j4) =
                *(const float4*)(kp + (size_t)d * SSP + t0 + 4 * j4);
        }
        __syncthreads();

        // S[i][j] = sum_d Q[d][i] * K[d][j]
        float s[4][4];
#pragma unroll
        for (int i = 0; i < 4; i++)
#pragma unroll
            for (int j = 0; j < 4; j++) s[i][j] = 0.f;
#pragma unroll 8
        for (int d = 0; d < 64; d++) {
            float a_[4], b_[4];
            *(float4*)a_ = *(float4*)(Qs + d * 64 + 4 * ty);   // broadcast
            *(float4*)b_ = *(float4*)(KVs + d * 64 + 4 * tx);  // conflict-free
#pragma unroll
            for (int i = 0; i < 4; i++)
#pragma unroll
                for (int j = 0; j < 4; j++) s[i][j] += a_[i] * b_[j];
        }

        // Online softmax per query row (reduce across 16 tx lanes)
#pragma unroll
        for (int i = 0; i < 4; i++) {
#pragma unroll
            for (int j = 0; j < 4; j++) s[i][j] *= scale;
            float mx = fmaxf(fmaxf(s[i][0], s[i][1]), fmaxf(s[i][2], s[i][3]));
#pragma unroll
            for (int o = 8; o > 0; o >>= 1)
                mx = fmaxf(mx, __shfl_xor_sync(0xffffffffu, mx, o, 16));
            float mnew = fmaxf(m_run[i], mx);
            float corr = __expf(m_run[i] - mnew);
            m_run[i] = mnew;
            float rs = 0.f;
#pragma unroll
            for (int j = 0; j < 4; j++) {
                s[i][j] = __expf(s[i][j] - mnew);
                rs += s[i][j];
            }
#pragma unroll
            for (int o = 8; o > 0; o >>= 1)
                rs += __shfl_xor_sync(0xffffffffu, rs, o, 16);
            l_run[i] = l_run[i] * corr + rs;
#pragma unroll
            for (int j = 0; j < 4; j++) acc[i][j] *= corr;
        }

        __syncthreads();  // everyone done reading K from KVs
        // Store P[i][j] (conflict-free float4 rows)
#pragma unroll
        for (int i = 0; i < 4; i++)
            *(float4*)(Ps + (4 * ty + i) * 64 + 4 * tx) =
                make_float4(s[i][0], s[i][1], s[i][2], s[i][3]);
        // Load V transposed into KVs as Vt[j][d], XOR-swizzled on f4 groups
#pragma unroll
        for (int r = 0; r < 4; r++) {
            int f = tid + 256 * r;
            int d = f >> 4, j4 = f & 15;
            float4 v = *(const float4*)(vp + (size_t)d * SSP + t0 + 4 * j4);
            float vv[4] = {v.x, v.y, v.z, v.w};
#pragma unroll
            for (int jj = 0; jj < 4; jj++) {
                int j = 4 * j4 + jj;
                KVs[j * 64 + 4 * (((d >> 2) ^ (j & 15))) + (d & 3)] = vv[jj];
            }
        }
        __syncthreads();

        // O[i][d] += sum_j P[i][j] * Vt[j][d]
#pragma unroll 4
        for (int j4 = 0; j4 < 16; j4++) {
            float pa[4][4], vb[4][4];
#pragma unroll
            for (int i = 0; i < 4; i++)
                *(float4*)pa[i] = *(float4*)(Ps + (4 * ty + i) * 64 + 4 * j4);
#pragma unroll
            for (int jj = 0; jj < 4; jj++) {
                int j = 4 * j4 + jj;
                *(float4*)vb[jj] = *(float4*)(KVs + j * 64 + 4 * (tx ^ (j & 15)));
            }
#pragma unroll
            for (int i = 0; i < 4; i++)
#pragma unroll
                for (int jj = 0; jj < 4; jj++)
#pragma unroll
                    for (int dd = 0; dd < 4; dd++)
                        acc[i][dd] += pa[i][jj] * vb[jj][dd];
        }
    }

    float inv[4];
#pragma unroll
    for (int i = 0; i < 4; i++) inv[i] = 1.f / l_run[i];
    float* ap = g_att + ((size_t)b * CCH + h * HD) * SSP;
#pragma unroll
    for (int dd = 0; dd < 4; dd++) {
        float4 o = make_float4(acc[0][dd] * inv[0], acc[1][dd] * inv[1],
                               acc[2][dd] * inv[2], acc[3][dd] * inv[3]);
        *(float4*)(ap + (size_t)(4 * tx + dd) * SSP + q0 + 4 * ty) = o;
    }
}

// ---------------------------------------------------------------------------
extern "C" void kernel_launch(void* const* d_in, const int* in_sizes, int n_in,
                              void* d_out, int out_size) {
    const float* x     = (const float*)d_in[0];
    const float* gamma = (const float*)d_in[1];
    const float* beta  = (const float*)d_in[2];
    const float* w_qkv = (const float*)d_in[3];
    const float* w_out = (const float*)d_in[4];
    const float* b_out = (const float*)d_in[5];
    float* out = (float*)d_out;

    gn_kernel<<<BATCH * NG, 256>>>(x, gamma, beta);
    qkv_gemm_kernel<<<dim3(SSP / 128, 3 * CCH / 128, BATCH), 256>>>(w_qkv);
    attn_kernel<<<dim3(SSP / 64, NH, BATCH), 256>>>();
    out_gemm_kernel<<<dim3(SSP / 128, CCH / 128, BATCH), 256>>>(w_out, b_out, x, out);
}

// round 2
// speedup vs baseline: 1.0022x; 1.0022x over previous
#include <cuda_runtime.h>

#define BATCH 2
#define CCH   512
#define SSP   2304
#define NH    8
#define HD    64
#define NG    32
#define CPG   16
#define EPSV  1e-5f

// Scratch (allocation-free rule: __device__ globals)
__device__ float g_norm[BATCH * CCH * SSP];        // 9.4 MB
__device__ float g_qkv [BATCH * 3 * CCH * SSP];    // 28.3 MB
__device__ float g_att [BATCH * CCH * SSP];        // 9.4 MB

// ---------------------------------------------------------------------------
// GroupNorm: one block per (batch, group). 16 ch x 2304 = 36864 floats/group.
// ---------------------------------------------------------------------------
__global__ void gn_kernel(const float* __restrict__ x,
                          const float* __restrict__ gamma,
                          const float* __restrict__ beta) {
    int b = blockIdx.x >> 5;
    int g = blockIdx.x & 31;
    const float4* xp = (const float4*)(x + (size_t)(b * CCH + g * CPG) * SSP);
    float4* op = (float4*)(g_norm + (size_t)(b * CCH + g * CPG) * SSP);
    int tid = threadIdx.x;
    const int n4 = CPG * SSP / 4;  // 9216

    float s0 = 0.f, s1 = 0.f;
    for (int i = tid; i < n4; i += 256) {
        float4 v = xp[i];
        s0 += v.x + v.y + v.z + v.w;
        s1 += v.x * v.x + v.y * v.y + v.z * v.z + v.w * v.w;
    }
#pragma unroll
    for (int o = 16; o > 0; o >>= 1) {
        s0 += __shfl_xor_sync(0xffffffffu, s0, o);
        s1 += __shfl_xor_sync(0xffffffffu, s1, o);
    }
    __shared__ float sm0[8], sm1[8];
    __shared__ float stat[2];
    int w = tid >> 5;
    if ((tid & 31) == 0) { sm0[w] = s0; sm1[w] = s1; }
    __syncthreads();
    if (tid == 0) {
        float a = 0.f, q = 0.f;
#pragma unroll
        for (int i = 0; i < 8; i++) { a += sm0[i]; q += sm1[i]; }
        float mean = a * (1.f / 36864.f);
        float var  = q * (1.f / 36864.f) - mean * mean;
        stat[0] = mean;
        stat[1] = rsqrtf(var + EPSV);
    }
    __syncthreads();
    float mean = stat[0], rstd = stat[1];
    for (int i = tid; i < n4; i += 256) {
        int c = g * CPG + i / 576;  // 576 = SSP/4, float4 never crosses channel
        float ga = gamma[c] * rstd;
        float be = beta[c] - mean * ga;
        float4 v = xp[i];
        v.x = v.x * ga + be; v.y = v.y * ga + be;
        v.z = v.z * ga + be; v.w = v.w * ga + be;
        op[i] = v;
    }
}

// ---------------------------------------------------------------------------
// SGEMM: C[M,N] = A[M,K] @ B[K,N] (+bias[M] +res[M,N]).
// 128x128 block tile, K-tile 8, 256 threads, 8x8 microtile (split 4+4 to keep
// LDS.128 conflict-free), register-prefetched global loads.
// ---------------------------------------------------------------------------
__device__ __forceinline__ void sgemm128(
    int M, int N, int K,
    const float* __restrict__ A,
    const float* __restrict__ Bp,
    float* __restrict__ Cp,
    const float* __restrict__ bias,
    const float* __restrict__ res) {
    __shared__ float As[8 * 128];
    __shared__ float Bs[8 * 128];
    int tid = threadIdx.x;
    int tx = tid & 15, ty = tid >> 4;
    int m0 = blockIdx.y * 128, n0 = blockIdx.x * 128;

    int arow = tid >> 1, akq = (tid & 1) * 4;      // A: [128 rows][8 k], f4 along k
    int brow = tid >> 5, bcol = (tid & 31) * 4;    // B: [8 k][128 n], f4 along n
    const float* Aptr = A + (size_t)(m0 + arow) * K + akq;
    const float* Bptr = Bp + (size_t)brow * N + n0 + bcol;

    float4 ra = *(const float4*)Aptr;
    float4 rb = *(const float4*)Bptr;

    float acc[8][8];
#pragma unroll
    for (int i = 0; i < 8; i++)
#pragma unroll
        for (int j = 0; j < 8; j++) acc[i][j] = 0.f;

    int nkt = K >> 3;
    for (int kt = 0; kt < nkt; kt++) {
        As[(akq + 0) * 128 + arow] = ra.x;
        As[(akq + 1) * 128 + arow] = ra.y;
        As[(akq + 2) * 128 + arow] = ra.z;
        As[(akq + 3) * 128 + arow] = ra.w;
        *(float4*)(Bs + brow * 128 + bcol) = rb;
        __syncthreads();
        if (kt + 1 < nkt) {
            ra = *(const float4*)(Aptr + (kt + 1) * 8);
            rb = *(const float4*)(Bptr + (size_t)(kt + 1) * 8 * N);
        }
#pragma unroll
        for (int kk = 0; kk < 8; kk++) {
            float a_[8], b_[8];
            *(float4*)&a_[0] = *(float4*)(As + kk * 128 + 4 * ty);
            *(float4*)&a_[4] = *(float4*)(As + kk * 128 + 64 + 4 * ty);
            *(float4*)&b_[0] = *(float4*)(Bs + kk * 128 + 4 * tx);
            *(float4*)&b_[4] = *(float4*)(Bs + kk * 128 + 64 + 4 * tx);
#pragma unroll
            for (int i = 0; i < 8; i++)
#pragma unroll
                for (int j = 0; j < 8; j++) acc[i][j] += a_[i] * b_[j];
        }
        __syncthreads();
    }

#pragma unroll
    for (int ih = 0; ih < 2; ih++) {
#pragma unroll
        for (int ii = 0; ii < 4; ii++) {
            int m = m0 + ih * 64 + 4 * ty + ii;
            float bv = bias ? bias[m] : 0.f;
#pragma unroll
            for (int jh = 0; jh < 2; jh++) {
                int n = n0 + jh * 64 + 4 * tx;
                float4 o;
                o.x = acc[ih * 4 + ii][jh * 4 + 0] + bv;
                o.y = acc[ih * 4 + ii][jh * 4 + 1] + bv;
                o.z = acc[ih * 4 + ii][jh * 4 + 2] + bv;
                o.w = acc[ih * 4 + ii][jh * 4 + 3] + bv;
                if (res) {
                    float4 r = *(const float4*)(res + (size_t)m * N + n);
                    o.x += r.x; o.y += r.y; o.z += r.z; o.w += r.w;
                }
                *(float4*)(Cp + (size_t)m * N + n) = o;
            }
        }
    }
}

__global__ void __launch_bounds__(256) qkv_gemm_kernel(const float* __restrict__ w_qkv) {
    int b = blockIdx.z;
    sgemm128(3 * CCH, SSP, CCH, w_qkv,
             g_norm + (size_t)b * CCH * SSP,
             g_qkv + (size_t)b * 3 * CCH * SSP,
             nullptr, nullptr);
}

__global__ void __launch_bounds__(256) out_gemm_kernel(const float* __restrict__ w_out,
                                                       const float* __restrict__ b_out,
                                                       const float* __restrict__ x,
                                                       float* __restrict__ out) {
    int b = blockIdx.z;
    sgemm128(CCH, SSP, CCH, w_out,
             g_att + (size_t)b * CCH * SSP,
             out + (size_t)b * CCH * SSP,
             b_out, x + (size_t)b * CCH * SSP);
}

// ---------------------------------------------------------------------------
// Flash attention, fp32. Block = 64 queries of one (b,h). 256 threads (16x16),
// 4x4 microtiles. Online softmax with width-16 shuffle row reductions.
// SMEM: Qs[d][i], KVs (K as [d][j], then V transposed+XOR-swizzled [j][d]),
// Ps[i][j]. 3 x 16KB = exactly 48KB static.
// ---------------------------------------------------------------------------
__global__ void __launch_bounds__(256) attn_kernel() {
    __shared__ float Qs[64 * 64];
    __shared__ float KVs[64 * 64];
    __shared__ float Ps[64 * 64];
    int tid = threadIdx.x;
    int tx = tid & 15, ty = tid >> 4;
    int qt = blockIdx.x, h = blockIdx.y, b = blockIdx.z;
    const float* base = g_qkv + ((size_t)b * 3 * CCH + h * 3 * HD) * SSP;
    const float* qp = base;
    const float* kp = base + (size_t)HD * SSP;
    const float* vp = base + (size_t)2 * HD * SSP;
    int q0 = qt * 64;

    // Load Q tile [d=64][i=64], coalesced along i.
#pragma unroll
    for (int r = 0; r < 4; r++) {
        int f = tid + 256 * r;
        int d = f >> 4, i4 = f & 15;
        *(float4*)(Qs + d * 64 + 4 * i4) =
            *(const float4*)(qp + (size_t)d * SSP + q0 + 4 * i4);
    }

    float m_run[4], l_run[4], acc[4][4];
#pragma unroll
    for (int i = 0; i < 4; i++) {
        m_run[i] = -1e30f; l_run[i] = 0.f;
#pragma unroll
        for (int j = 0; j < 4; j++) acc[i][j] = 0.f;
    }
    const float scale = 0.044194173824159216f;  // 1/sqrt(512)

    for (int t = 0; t < SSP / 64; t++) {
        int t0 = t * 64;
        __syncthreads();  // prev-iter Ps/Vt reads done; Q visible for t=0
        // Load K tile [d][j]
#pragma unroll
        for (int r = 0; r < 4; r++) {
            int f = tid + 256 * r;
            int d = f >> 4, j4 = f & 15;
            *(float4*)(KVs + d * 64 + 4 * j4) =
                *(const float4*)(kp + (size_t)d * SSP + t0 + 4 * j4);
        }
        __syncthreads();

        // S[i][j] = sum_d Q[d][i] * K[d][j]
        float s[4][4];
#pragma unroll
        for (int i = 0; i < 4; i++)
#pragma unroll
            for (int j = 0; j < 4; j++) s[i][j] = 0.f;
#pragma unroll 8
        for (int d = 0; d < 64; d++) {
            float a_[4], b_[4];
            *(float4*)a_ = *(float4*)(Qs + d * 64 + 4 * ty);   // broadcast
            *(float4*)b_ = *(float4*)(KVs + d * 64 + 4 * tx);  // conflict-free
#pragma unroll
            for (int i = 0; i < 4; i++)
#pragma unroll
                for (int j = 0; j < 4; j++) s[i][j] += a_[i] * b_[j];
        }

        // Online softmax per query row (reduce across 16 tx lanes)
#pragma unroll
        for (int i = 0; i < 4; i++) {
#pragma unroll
            for (int j = 0; j < 4; j++) s[i][j] *= scale;
            float mx = fmaxf(fmaxf(s[i][0], s[i][1]), fmaxf(s[i][2], s[i][3]));
#pragma unroll
            for (int o = 8; o > 0; o >>= 1)
                mx = fmaxf(mx, __shfl_xor_sync(0xffffffffu, mx, o, 16));
            float mnew = fmaxf(m_run[i], mx);
            float corr = __expf(m_run[i] - mnew);
            m_run[i] = mnew;
            float rs = 0.f;
#pragma unroll
            for (int j = 0; j < 4; j++) {
                s[i][j] = __expf(s[i][j] - mnew);
                rs += s[i][j];
            }
#pragma unroll
            for (int o = 8; o > 0; o >>= 1)
                rs += __shfl_xor_sync(0xffffffffu, rs, o, 16);
            l_run[i] = l_run[i] * corr + rs;
#pragma unroll
            for (int j = 0; j < 4; j++) acc[i][j] *= corr;
        }

        __syncthreads();  // everyone done reading K from KVs
        // Store P[i][j] (conflict-free float4 rows)
#pragma unroll
        for (int i = 0; i < 4; i++)
            *(float4*)(Ps + (4 * ty + i) * 64 + 4 * tx) =
                make_float4(s[i][0], s[i][1], s[i][2], s[i][3]);
        // Load V transposed into KVs as Vt[j][d], XOR-swizzled on f4 groups
#pragma unroll
        for (int r = 0; r < 4; r++) {
            int f = tid + 256 * r;
            int d = f >> 4, j4 = f & 15;
            float4 v = *(const float4*)(vp + (size_t)d * SSP + t0 + 4 * j4);
            float vv[4] = {v.x, v.y, v.z, v.w};
#pragma unroll
            for (int jj = 0; jj < 4; jj++) {
                int j = 4 * j4 + jj;
                KVs[j * 64 + 4 * (((d >> 2) ^ (j & 15))) + (d & 3)] = vv[jj];
            }
        }
        __syncthreads();

        // O[i][d] += sum_j P[i][j] * Vt[j][d]
#pragma unroll 4
        for (int j4 = 0; j4 < 16; j4++) {
            float pa[4][4], vb[4][4];
#pragma unroll
            for (int i = 0; i < 4; i++)
                *(float4*)pa[i] = *(float4*)(Ps + (4 * ty + i) * 64 + 4 * j4);
#pragma unroll
            for (int jj = 0; jj < 4; jj++) {
                int j = 4 * j4 + jj;
                *(float4*)vb[jj] = *(float4*)(KVs + j * 64 + 4 * (tx ^ (j & 15)));
            }
#pragma unroll
            for (int i = 0; i < 4; i++)
#pragma unroll
                for (int jj = 0; jj < 4; jj++)
#pragma unroll
                    for (int dd = 0; dd < 4; dd++)
                        acc[i][dd] += pa[i][jj] * vb[jj][dd];
        }
    }

    float inv[4];
#pragma unroll
    for (int i = 0; i < 4; i++) inv[i] = 1.f / l_run[i];
    float* ap = g_att + ((size_t)b * CCH + h * HD) * SSP;
#pragma unroll
    for (int dd = 0; dd < 4; dd++) {
        float4 o = make_float4(acc[0][dd] * inv[0], acc[1][dd] * inv[1],
                               acc[2][dd] * inv[2], acc[3][dd] * inv[3]);
        *(float4*)(ap + (size_t)(4 * tx + dd) * SSP + q0 + 4 * ty) = o;
    }
}

// ---------------------------------------------------------------------------
extern "C" void kernel_launch(void* const* d_in, const int* in_sizes, int n_in,
                              void* d_out, int out_size) {
    const float* x     = (const float*)d_in[0];
    const float* gamma = (const float*)d_in[1];
    const float* beta  = (const float*)d_in[2];
    const float* w_qkv = (const float*)d_in[3];
    const float* w_out = (const float*)d_in[4];
    const float* b_out = (const float*)d_in[5];
    float* out = (float*)d_out;

    gn_kernel<<<BATCH * NG, 256>>>(x, gamma, beta);
    qkv_gemm_kernel<<<dim3(SSP / 128, 3 * CCH / 128, BATCH), 256>>>(w_qkv);
    attn_kernel<<<dim3(SSP / 64, NH, BATCH), 256>>>();
    out_gemm_kernel<<<dim3(SSP / 128, CCH / 128, BATCH), 256>>>(w_out, b_out, x, out);
}

// round 3
// speedup vs baseline: 2.2930x; 2.2880x over previous
#include <cuda_runtime.h>
#include <cstdint>

#define BATCH 2
#define CCH   512
#define SSP   2304
#define NH    8
#define HD    64
#define NG    32
#define CPG   16
#define EPSV  1e-5f

// Scratch (allocation-free rule: __device__ globals)
__device__ float g_norm[BATCH * CCH * SSP];        // 9.4 MB
__device__ float g_qkv [BATCH * 3 * CCH * SSP];    // 28.3 MB
__device__ float g_att [BATCH * CCH * SSP];        // 9.4 MB

// ---------------------------------------------------------------------------
// tf32 helpers
// ---------------------------------------------------------------------------
__device__ __forceinline__ unsigned f2tf(float f) {
    unsigned u;
    asm("cvt.rna.tf32.f32 %0, %1;" : "=r"(u) : "f"(f));
    return u;
}

__device__ __forceinline__ void mma_tf32(float d[4], const unsigned a[4],
                                         const unsigned b[2], const float c[4]) {
    asm volatile(
        "mma.sync.aligned.m16n8k8.row.col.f32.tf32.tf32.f32 "
        "{%0,%1,%2,%3}, {%4,%5,%6,%7}, {%8,%9}, {%10,%11,%12,%13};\n"
        : "=f"(d[0]), "=f"(d[1]), "=f"(d[2]), "=f"(d[3])
        : "r"(a[0]), "r"(a[1]), "r"(a[2]), "r"(a[3]),
          "r"(b[0]), "r"(b[1]),
          "f"(c[0]), "f"(c[1]), "f"(c[2]), "f"(c[3]));
}

// ---------------------------------------------------------------------------
// GroupNorm: one block per (batch, group). 16 ch x 2304 = 36864 floats/group.
// ---------------------------------------------------------------------------
__global__ void gn_kernel(const float* __restrict__ x,
                          const float* __restrict__ gamma,
                          const float* __restrict__ beta) {
    int b = blockIdx.x >> 5;
    int g = blockIdx.x & 31;
    const float4* xp = (const float4*)(x + (size_t)(b * CCH + g * CPG) * SSP);
    float4* op = (float4*)(g_norm + (size_t)(b * CCH + g * CPG) * SSP);
    int tid = threadIdx.x;
    const int n4 = CPG * SSP / 4;  // 9216

    float s0 = 0.f, s1 = 0.f;
    for (int i = tid; i < n4; i += 256) {
        float4 v = xp[i];
        s0 += v.x + v.y + v.z + v.w;
        s1 += v.x * v.x + v.y * v.y + v.z * v.z + v.w * v.w;
    }
#pragma unroll
    for (int o = 16; o > 0; o >>= 1) {
        s0 += __shfl_xor_sync(0xffffffffu, s0, o);
        s1 += __shfl_xor_sync(0xffffffffu, s1, o);
    }
    __shared__ float sm0[8], sm1[8];
    __shared__ float stat[2];
    int w = tid >> 5;
    if ((tid & 31) == 0) { sm0[w] = s0; sm1[w] = s1; }
    __syncthreads();
    if (tid == 0) {
        float a = 0.f, q = 0.f;
#pragma unroll
        for (int i = 0; i < 8; i++) { a += sm0[i]; q += sm1[i]; }
        float mean = a * (1.f / 36864.f);
        float var  = q * (1.f / 36864.f) - mean * mean;
        stat[0] = mean;
        stat[1] = rsqrtf(var + EPSV);
    }
    __syncthreads();
    float mean = stat[0], rstd = stat[1];
    for (int i = tid; i < n4; i += 256) {
        int c = g * CPG + i / 576;  // 576 = SSP/4, float4 never crosses channel
        float ga = gamma[c] * rstd;
        float be = beta[c] - mean * ga;
        float4 v = xp[i];
        v.x = v.x * ga + be; v.y = v.y * ga + be;
        v.z = v.z * ga + be; v.w = v.w * ga + be;
        op[i] = v;
    }
}

// ---------------------------------------------------------------------------
// tf32 tensor-core GEMM: C[M,N] = A[M,K] @ B[K,N] (+bias[M] +res[M,N]).
// 128x128 block tile, ktile 32, 256 threads = 8 warps (2M x 4N), warp 64x32.
// SMEM holds pre-converted tf32 bits; A stored k-major [k][136] so that
// scattered frag LDS are conflict-free (stride 136 == 8 mod 32).
// ---------------------------------------------------------------------------
#define LDT 136

__device__ __forceinline__ void mmagemm(
    int M, int N, int K,
    const float* __restrict__ A,
    const float* __restrict__ Bp,
    float* __restrict__ Cp,
    const float* __restrict__ bias,
    const float* __restrict__ res) {
    __shared__ unsigned As[32 * LDT];
    __shared__ unsigned Bs[32 * LDT];
    int tid = threadIdx.x;
    int lane = tid & 31, wid = tid >> 5;
    int wm = (wid >> 2) * 64, wn = (wid & 3) * 32;
    int m0 = blockIdx.y * 128, n0 = blockIdx.x * 128;
    int r0 = lane >> 2, c2 = lane & 3;

    // A loader: thread covers row am, k = akq + r*8 + 0..3
    int am = tid & 127, akq = (tid >> 7) * 4;
    const float* Ap = A + (size_t)(m0 + am) * K + akq;
    // B loader: 4-col group bn4, k-row bk + r*8
    int bn4 = (tid & 31) * 4, bk = tid >> 5;
    const float* Bptr = Bp + (size_t)bk * N + n0 + bn4;

    float4 ra[4], rb[4];
#pragma unroll
    for (int r = 0; r < 4; r++) {
        ra[r] = *(const float4*)(Ap + r * 8);
        rb[r] = *(const float4*)(Bptr + (size_t)r * 8 * N);
    }

    float acc[4][4][4];
#pragma unroll
    for (int mt = 0; mt < 4; mt++)
#pragma unroll
        for (int nt = 0; nt < 4; nt++)
#pragma unroll
            for (int e = 0; e < 4; e++) acc[mt][nt][e] = 0.f;

    int nkt = K >> 5;
    for (int kt = 0; kt < nkt; kt++) {
#pragma unroll
        for (int r = 0; r < 4; r++) {
            int k = akq + r * 8;
            As[(k + 0) * LDT + am] = f2tf(ra[r].x);
            As[(k + 1) * LDT + am] = f2tf(ra[r].y);
            As[(k + 2) * LDT + am] = f2tf(ra[r].z);
            As[(k + 3) * LDT + am] = f2tf(ra[r].w);
            uint4 ub;
            ub.x = f2tf(rb[r].x); ub.y = f2tf(rb[r].y);
            ub.z = f2tf(rb[r].z); ub.w = f2tf(rb[r].w);
            *(uint4*)&Bs[(bk + r * 8) * LDT + bn4] = ub;
        }
        __syncthreads();
        if (kt + 1 < nkt) {
#pragma unroll
            for (int r = 0; r < 4; r++) {
                ra[r] = *(const float4*)(Ap + (kt + 1) * 32 + r * 8);
                rb[r] = *(const float4*)(Bptr + (size_t)((kt + 1) * 32 + r * 8) * N);
            }
        }
#pragma unroll
        for (int ks = 0; ks < 4; ks++) {
            int k8 = ks * 8;
            unsigned af[4][4];
#pragma unroll
            for (int mt = 0; mt < 4; mt++) {
                int mm = wm + mt * 16 + r0;
                af[mt][0] = As[(k8 + c2) * LDT + mm];
                af[mt][1] = As[(k8 + c2) * LDT + mm + 8];
                af[mt][2] = As[(k8 + 4 + c2) * LDT + mm];
                af[mt][3] = As[(k8 + 4 + c2) * LDT + mm + 8];
            }
            unsigned bf[4][2];
#pragma unroll
            for (int nt = 0; nt < 4; nt++) {
                int nn = wn + nt * 8 + r0;
                bf[nt][0] = Bs[(k8 + c2) * LDT + nn];
                bf[nt][1] = Bs[(k8 + 4 + c2) * LDT + nn];
            }
#pragma unroll
            for (int mt = 0; mt < 4; mt++)
#pragma unroll
                for (int nt = 0; nt < 4; nt++)
                    mma_tf32(acc[mt][nt], af[mt], bf[nt], acc[mt][nt]);
        }
        __syncthreads();
    }

    // Epilogue: c0/c1 at (row, 2c), c2/c3 at (row+8, 2c)
#pragma unroll
    for (int mt = 0; mt < 4; mt++) {
        int mA = m0 + wm + mt * 16 + r0;
        float bv0 = bias ? bias[mA] : 0.f;
        float bv1 = bias ? bias[mA + 8] : 0.f;
#pragma unroll
        for (int nt = 0; nt < 4; nt++) {
            int n = n0 + wn + nt * 8 + 2 * c2;
            float2 o0, o1;
            o0.x = acc[mt][nt][0] + bv0; o0.y = acc[mt][nt][1] + bv0;
            o1.x = acc[mt][nt][2] + bv1; o1.y = acc[mt][nt][3] + bv1;
            if (res) {
                float2 q0v = *(const float2*)(res + (size_t)mA * N + n);
                float2 q1v = *(const float2*)(res + (size_t)(mA + 8) * N + n);
                o0.x += q0v.x; o0.y += q0v.y;
                o1.x += q1v.x; o1.y += q1v.y;
            }
            *(float2*)(Cp + (size_t)mA * N + n) = o0;
            *(float2*)(Cp + (size_t)(mA + 8) * N + n) = o1;
        }
    }
}

__global__ void __launch_bounds__(256) qkv_gemm_kernel(const float* __restrict__ w_qkv) {
    int b = blockIdx.z;
    mmagemm(3 * CCH, SSP, CCH, w_qkv,
            g_norm + (size_t)b * CCH * SSP,
            g_qkv + (size_t)b * 3 * CCH * SSP,
            nullptr, nullptr);
}

__global__ void __launch_bounds__(256) out_gemm_kernel(const float* __restrict__ w_out,
                                                       const float* __restrict__ b_out,
                                                       const float* __restrict__ x,
                                                       float* __restrict__ out) {
    int b = blockIdx.z;
    mmagemm(CCH, SSP, CCH, w_out,
            g_att + (size_t)b * CCH * SSP,
            out + (size_t)b * CCH * SSP,
            b_out, x + (size_t)b * CCH * SSP);
}

// ---------------------------------------------------------------------------
// Flash attention with tf32 mma. Block = 64 queries of one (b,h), 128 threads
// (4 warps, each owning 16 query rows). K-tiles of 64 keys.
// SMEM (dynamic, 70KB): Qs[64d][72], Ks[64d][72], Vs[64d][68], Ps[64i][68]
// all storing pre-converted tf32 bits. Strides chosen so every scattered
// fragment LDS.32 is bank-conflict-free.
// ---------------------------------------------------------------------------
__global__ void __launch_bounds__(128) attn_kernel() {
    extern __shared__ unsigned smem_u[];
    unsigned* Qs = smem_u;                           // [64][72]
    unsigned* Ks = smem_u + 64 * 72;                 // [64][72]
    unsigned* Vs = smem_u + 2 * 64 * 72;             // [64][68]
    unsigned* Ps = smem_u + 2 * 64 * 72 + 64 * 68;   // [64][68]

    int tid = threadIdx.x, lane = tid & 31, w = tid >> 5;
    int r0 = lane >> 2, c2 = lane & 3;
    int qt = blockIdx.x, h = blockIdx.y, b = blockIdx.z;
    const float* base = g_qkv + ((size_t)b * 3 * CCH + h * 3 * HD) * SSP;
    const float* qp = base;
    const float* kp = base + (size_t)HD * SSP;
    const float* vp = base + (size_t)2 * HD * SSP;
    int q0 = qt * 64;
    const float scale = 0.044194173824159216f;  // 1/sqrt(512)

    // Load Q tile [d][i], fold in softmax scale, convert to tf32.
#pragma unroll
    for (int r = 0; r < 8; r++) {
        int f = tid + 128 * r;
        int d = f >> 4, i4 = (f & 15) * 4;
        float4 v = *(const float4*)(qp + (size_t)d * SSP + q0 + i4);
        uint4 u;
        u.x = f2tf(v.x * scale); u.y = f2tf(v.y * scale);
        u.z = f2tf(v.z * scale); u.w = f2tf(v.w * scale);
        *(uint4*)&Qs[d * 72 + i4] = u;
    }

    float m_run[2] = {-1e30f, -1e30f}, l_run[2] = {0.f, 0.f};
    float o[8][4];
#pragma unroll
    for (int nt = 0; nt < 8; nt++)
#pragma unroll
        for (int e = 0; e < 4; e++) o[nt][e] = 0.f;

    int iP = w * 16 + r0;  // this thread's base query row within the 64-tile

    for (int t = 0; t < SSP / 64; t++) {
        int t0 = t * 64;
        __syncthreads();  // prior iter's Vs/Ks reads complete (Q visible t=0)
        // Load K and V tiles, converting to tf32.
#pragma unroll
        for (int r = 0; r < 8; r++) {
            int f = tid + 128 * r;
            int d = f >> 4, j4 = (f & 15) * 4;
            float4 kv = *(const float4*)(kp + (size_t)d * SSP + t0 + j4);
            uint4 uk;
            uk.x = f2tf(kv.x); uk.y = f2tf(kv.y);
            uk.z = f2tf(kv.z); uk.w = f2tf(kv.w);
            *(uint4*)&Ks[d * 72 + j4] = uk;
            float4 vv = *(const float4*)(vp + (size_t)d * SSP + t0 + j4);
            uint4 uv;
            uv.x = f2tf(vv.x); uv.y = f2tf(vv.y);
            uv.z = f2tf(vv.z); uv.w = f2tf(vv.w);
            *(uint4*)&Vs[d * 68 + j4] = uv;
        }
        __syncthreads();

        // S = (Q*scale) K^T  -- warp computes its 16 rows x 64 keys.
        float s[8][4];
#pragma unroll
        for (int nt = 0; nt < 8; nt++)
#pragma unroll
            for (int e = 0; e < 4; e++) s[nt][e] = 0.f;
#pragma unroll
        for (int ks = 0; ks < 8; ks++) {
            int k8 = ks * 8;
            unsigned a[4];
            a[0] = Qs[(k8 + c2) * 72 + iP];
            a[1] = Qs[(k8 + c2) * 72 + iP + 8];
            a[2] = Qs[(k8 + 4 + c2) * 72 + iP];
            a[3] = Qs[(k8 + 4 + c2) * 72 + iP + 8];
#pragma unroll
            for (int nt = 0; nt < 8; nt++) {
                int j = nt * 8 + r0;
                unsigned bb[2];
                bb[0] = Ks[(k8 + c2) * 72 + j];
                bb[1] = Ks[(k8 + 4 + c2) * 72 + j];
                mma_tf32(s[nt], a, bb, s[nt]);
            }
        }

        // Online softmax: row0 = iP (regs 0,1), row1 = iP+8 (regs 2,3).
        float mx0 = -1e30f, mx1 = -1e30f;
#pragma unroll
        for (int nt = 0; nt < 8; nt++) {
            mx0 = fmaxf(mx0, fmaxf(s[nt][0], s[nt][1]));
            mx1 = fmaxf(mx1, fmaxf(s[nt][2], s[nt][3]));
        }
#pragma unroll
        for (int off = 1; off <= 2; off <<= 1) {
            mx0 = fmaxf(mx0, __shfl_xor_sync(0xffffffffu, mx0, off));
            mx1 = fmaxf(mx1, __shfl_xor_sync(0xffffffffu, mx1, off));
        }
        float mn0 = fmaxf(m_run[0], mx0);
        float mn1 = fmaxf(m_run[1], mx1);
        float cr0 = __expf(m_run[0] - mn0);
        float cr1 = __expf(m_run[1] - mn1);
        m_run[0] = mn0; m_run[1] = mn1;
        float sum0 = 0.f, sum1 = 0.f;
#pragma unroll
        for (int nt = 0; nt < 8; nt++) {
            s[nt][0] = __expf(s[nt][0] - mn0);
            s[nt][1] = __expf(s[nt][1] - mn0);
            s[nt][2] = __expf(s[nt][2] - mn1);
            s[nt][3] = __expf(s[nt][3] - mn1);
            sum0 += s[nt][0] + s[nt][1];
            sum1 += s[nt][2] + s[nt][3];
        }
#pragma unroll
        for (int off = 1; off <= 2; off <<= 1) {
            sum0 += __shfl_xor_sync(0xffffffffu, sum0, off);
            sum1 += __shfl_xor_sync(0xffffffffu, sum1, off);
        }
        l_run[0] = l_run[0] * cr0 + sum0;
        l_run[1] = l_run[1] * cr1 + sum1;
#pragma unroll
        for (int nt = 0; nt < 8; nt++) {
            o[nt][0] *= cr0; o[nt][1] *= cr0;
            o[nt][2] *= cr1; o[nt][3] *= cr1;
        }

        // Store P (own rows only) as tf32.
#pragma unroll
        for (int nt = 0; nt < 8; nt++) {
            int j = nt * 8 + 2 * c2;
            uint2 p0, p1;
            p0.x = f2tf(s[nt][0]); p0.y = f2tf(s[nt][1]);
            p1.x = f2tf(s[nt][2]); p1.y = f2tf(s[nt][3]);
            *(uint2*)&Ps[iP * 68 + j] = p0;
            *(uint2*)&Ps[(iP + 8) * 68 + j] = p1;
        }
        __syncwarp();

        // O += P V  (A = P rows of this warp, B = V[j][dd] read transposed)
#pragma unroll
        for (int ks = 0; ks < 8; ks++) {
            int k8 = ks * 8;
            unsigned a[4];
            a[0] = Ps[iP * 68 + k8 + c2];
            a[1] = Ps[(iP + 8) * 68 + k8 + c2];
            a[2] = Ps[iP * 68 + k8 + 4 + c2];
            a[3] = Ps[(iP + 8) * 68 + k8 + 4 + c2];
#pragma unroll
            for (int nt = 0; nt < 8; nt++) {
                int dd = nt * 8 + r0;
                unsigned bb[2];
                bb[0] = Vs[dd * 68 + k8 + c2];
                bb[1] = Vs[dd * 68 + k8 + 4 + c2];
                mma_tf32(o[nt], a, bb, o[nt]);
            }
        }
    }

    // Finalize: divide by l, stage through SMEM (reuse Ks) for coalesced out.
    float inv0 = 1.f / l_run[0], inv1 = 1.f / l_run[1];
    __syncthreads();
    float* Os = (float*)Ks;  // [64 dd][72]
#pragma unroll
    for (int nt = 0; nt < 8; nt++) {
        int dd = nt * 8 + 2 * c2;
        Os[dd * 72 + iP]           = o[nt][0] * inv0;
        Os[(dd + 1) * 72 + iP]     = o[nt][1] * inv0;
        Os[dd * 72 + iP + 8]       = o[nt][2] * inv1;
        Os[(dd + 1) * 72 + iP + 8] = o[nt][3] * inv1;
    }
    __syncthreads();
    float* ap = g_att + ((size_t)b * CCH + h * HD) * SSP;
#pragma unroll
    for (int r = 0; r < 8; r++) {
        int f = tid + 128 * r;
        int d = f >> 4, i4 = (f & 15) * 4;
        *(float4*)(ap + (size_t)d * SSP + q0 + i4) = *(float4*)&Os[d * 72 + i4];
    }
}

// ---------------------------------------------------------------------------
extern "C" void kernel_launch(void* const* d_in, const int* in_sizes, int n_in,
                              void* d_out, int out_size) {
    const float* x     = (const float*)d_in[0];
    const float* gamma = (const float*)d_in[1];
    const float* beta  = (const float*)d_in[2];
    const float* w_qkv = (const float*)d_in[3];
    const float* w_out = (const float*)d_in[4];
    const float* b_out = (const float*)d_in[5];
    float* out = (float*)d_out;

    const int attn_smem = (2 * 64 * 72 + 2 * 64 * 68) * 4;  // 71680 B
    cudaFuncSetAttribute(attn_kernel, cudaFuncAttributeMaxDynamicSharedMemorySize,
                         attn_smem);

    gn_kernel<<<BATCH * NG, 256>>>(x, gamma, beta);
    qkv_gemm_kernel<<<dim3(SSP / 128, 3 * CCH / 128, BATCH), 256>>>(w_qkv);
    attn_kernel<<<dim3(SSP / 64, NH, BATCH), 128, attn_smem>>>();
    out_gemm_kernel<<<dim3(SSP / 128, CCH / 128, BATCH), 256>>>(w_out, b_out, x, out);
}

// round 4
// speedup vs baseline: 6.0534x; 2.6400x over previous
#include <cuda_runtime.h>
#include <cuda_bf16.h>
#include <cstdint>

#define BATCH 2
#define CCH   512
#define SSP   2304
#define NH    8
#define HD    64
#define CPG   16
#define EPSV  1e-5f
#define SCALE 0.044194173824159216f  // 1/sqrt(512)

typedef __nv_bfloat16 bf16;

// Scratch (allocation-free rule: __device__ globals) — bf16 intermediates
__device__ bf16 g_norm[BATCH * CCH * SSP];
__device__ bf16 g_qkv [BATCH * 3 * CCH * SSP];
__device__ bf16 g_att [BATCH * CCH * SSP];
__device__ bf16 g_wqb [3 * CCH * CCH];
__device__ bf16 g_wob [CCH * CCH];

// ---------------------------------------------------------------------------
// PTX helpers
// ---------------------------------------------------------------------------
__device__ __forceinline__ unsigned sptr(const void* p) {
    return (unsigned)__cvta_generic_to_shared(p);
}
__device__ __forceinline__ void ldsm_x4(unsigned r[4], unsigned a) {
    asm volatile("ldmatrix.sync.aligned.m8n8.x4.shared.b16 {%0,%1,%2,%3}, [%4];"
                 : "=r"(r[0]), "=r"(r[1]), "=r"(r[2]), "=r"(r[3]) : "r"(a));
}
__device__ __forceinline__ void ldsm_x4t(unsigned r[4], unsigned a) {
    asm volatile("ldmatrix.sync.aligned.m8n8.x4.trans.shared.b16 {%0,%1,%2,%3}, [%4];"
                 : "=r"(r[0]), "=r"(r[1]), "=r"(r[2]), "=r"(r[3]) : "r"(a));
}
__device__ __forceinline__ void mma_bf16(float d[4], const unsigned a[4],
                                         const unsigned b[2], const float c[4]) {
    asm volatile(
        "mma.sync.aligned.m16n8k16.row.col.f32.bf16.bf16.f32 "
        "{%0,%1,%2,%3}, {%4,%5,%6,%7}, {%8,%9}, {%10,%11,%12,%13};\n"
        : "=f"(d[0]), "=f"(d[1]), "=f"(d[2]), "=f"(d[3])
        : "r"(a[0]), "r"(a[1]), "r"(a[2]), "r"(a[3]), "r"(b[0]), "r"(b[1]),
          "f"(c[0]), "f"(c[1]), "f"(c[2]), "f"(c[3]));
}
#define CP16(dst, src) \
    asm volatile("cp.async.cg.shared.global [%0], [%1], 16;" :: "r"(dst), "l"(src) : "memory")
#define CP_COMMIT() asm volatile("cp.async.commit_group;" ::: "memory")
#define CP_WAIT1()  asm volatile("cp.async.wait_group 1;" ::: "memory")
#define CP_WAIT0()  asm volatile("cp.async.wait_group 0;" ::: "memory")

__device__ __forceinline__ bf16 tob(float f) { return __float2bfloat16_rn(f); }

// ---------------------------------------------------------------------------
// Weight conversion fp32 -> bf16 (runs once per launch; ~2us)
// ---------------------------------------------------------------------------
__global__ void wconv_kernel(const float* __restrict__ wq,
                             const float* __restrict__ wo) {
    int t = blockIdx.x * 256 + threadIdx.x;  // each handles 4 floats
    const int n1 = 3 * CCH * CCH / 4;        // 196608
    const int n2 = CCH * CCH / 4;            // 65536
    if (t < n1) {
        float4 v = ((const float4*)wq)[t];
        bf16* o = g_wqb + t * 4;
        o[0] = tob(v.x); o[1] = tob(v.y); o[2] = tob(v.z); o[3] = tob(v.w);
    } else if (t < n1 + n2) {
        int u = t - n1;
        float4 v = ((const float4*)wo)[u];
        bf16* o = g_wob + u * 4;
        o[0] = tob(v.x); o[1] = tob(v.y); o[2] = tob(v.z); o[3] = tob(v.w);
    }
}

// ---------------------------------------------------------------------------
// GroupNorm -> bf16
// ---------------------------------------------------------------------------
__global__ void gn_kernel(const float* __restrict__ x,
                          const float* __restrict__ gamma,
                          const float* __restrict__ beta) {
    int b = blockIdx.x >> 5;
    int g = blockIdx.x & 31;
    const float4* xp = (const float4*)(x + (size_t)(b * CCH + g * CPG) * SSP);
    bf16* op = g_norm + (size_t)(b * CCH + g * CPG) * SSP;
    int tid = threadIdx.x;
    const int n4 = CPG * SSP / 4;  // 9216

    float s0 = 0.f, s1 = 0.f;
    for (int i = tid; i < n4; i += 256) {
        float4 v = xp[i];
        s0 += v.x + v.y + v.z + v.w;
        s1 += v.x * v.x + v.y * v.y + v.z * v.z + v.w * v.w;
    }
#pragma unroll
    for (int o = 16; o > 0; o >>= 1) {
        s0 += __shfl_xor_sync(0xffffffffu, s0, o);
        s1 += __shfl_xor_sync(0xffffffffu, s1, o);
    }
    __shared__ float sm0[8], sm1[8], stat[2];
    int w = tid >> 5;
    if ((tid & 31) == 0) { sm0[w] = s0; sm1[w] = s1; }
    __syncthreads();
    if (tid == 0) {
        float a = 0.f, q = 0.f;
#pragma unroll
        for (int i = 0; i < 8; i++) { a += sm0[i]; q += sm1[i]; }
        float mean = a * (1.f / 36864.f);
        float var  = q * (1.f / 36864.f) - mean * mean;
        stat[0] = mean;
        stat[1] = rsqrtf(var + EPSV);
    }
    __syncthreads();
    float mean = stat[0], rstd = stat[1];
    for (int i = tid; i < n4; i += 256) {
        int c = g * CPG + i / 576;
        float ga = gamma[c] * rstd;
        float be = beta[c] - mean * ga;
        float4 v = xp[i];
        bf16 o4[4];
        o4[0] = tob(v.x * ga + be); o4[1] = tob(v.y * ga + be);
        o4[2] = tob(v.z * ga + be); o4[3] = tob(v.w * ga + be);
        *(uint2*)(op + i * 4) = *(uint2*)o4;
    }
}

// ---------------------------------------------------------------------------
// bf16 tensor-core GEMM: C[M,N] = A[M,K] @ B[K,N]. 128x128 tile, ktile 32,
// 256 thr = 8 warps (2Mx4N), warp 64x32. cp.async 2-stage double buffer.
// As [m][k] stride 40, Bs [k][n] stride 136 (both ldmatrix conflict-free).
// qscale: rows with (m%192)<64 scaled (folds softmax scale into Q).
// ---------------------------------------------------------------------------
#define AST 40
#define BST 136

__device__ __forceinline__ void gemm_core(
    int M, int N, int K,
    const bf16* __restrict__ A, const bf16* __restrict__ Bp,
    bf16* __restrict__ Cb, float* __restrict__ Cf,
    const float* __restrict__ bias, const float* __restrict__ res,
    bool qscale) {
    __shared__ bf16 As[2][128 * AST];
    __shared__ bf16 Bs[2][32 * BST];
    int tid = threadIdx.x;
    int lane = tid & 31, wid = tid >> 5;
    int wm = (wid >> 2) * 64, wn = (wid & 3) * 32;
    int m0 = blockIdx.y * 128, n0 = blockIdx.x * 128;
    int r0 = lane >> 2, c2 = lane & 3;

    int lm = tid >> 2, lko = (tid & 3) * 8;     // A loader: 64 rows/round, 2 rounds
    int lk = tid >> 4, lno = (tid & 15) * 8;    // B loader: 16 rows/round, 2 rounds

    const bf16* Ag = A + (size_t)(m0 + lm) * K + lko;
    const bf16* Bg = Bp + (size_t)lk * N + n0 + lno;

    // precomputed ldmatrix lane addresses (element offsets)
    int a_m = ((lane >> 3) & 1) * 8 + (lane & 7);
    int a_k = ((lane >> 4) & 1) * 8;
    int b_k = ((lane >> 3) & 1) * 8 + (lane & 7);
    int b_n = ((lane >> 4) & 1) * 8;

    float acc[4][4][4];
#pragma unroll
    for (int mt = 0; mt < 4; mt++)
#pragma unroll
        for (int nt = 0; nt < 4; nt++)
#pragma unroll
            for (int e = 0; e < 4; e++) acc[mt][nt][e] = 0.f;

    int nkt = K >> 5;  // 16
    // preload tile 0
#pragma unroll
    for (int r = 0; r < 2; r++) {
        CP16(sptr(&As[0][(lm + r * 64) * AST + lko]), Ag + (size_t)r * 64 * K);
        CP16(sptr(&Bs[0][(lk + r * 16) * BST + lno]), Bg + (size_t)r * 16 * N);
    }
    CP_COMMIT();

    for (int kt = 0; kt < nkt; kt++) {
        int buf = kt & 1;
        if (kt + 1 < nkt) {
            int nb = buf ^ 1;
#pragma unroll
            for (int r = 0; r < 2; r++) {
                CP16(sptr(&As[nb][(lm + r * 64) * AST + lko]),
                     Ag + (size_t)(kt + 1) * 32 + (size_t)r * 64 * K);
                CP16(sptr(&Bs[nb][(lk + r * 16) * BST + lno]),
                     Bg + (size_t)((kt + 1) * 32 + r * 16) * N);
            }
            CP_COMMIT();
            CP_WAIT1();
        } else {
            CP_WAIT0();
        }
        __syncthreads();

#pragma unroll
        for (int ks = 0; ks < 2; ks++) {
            unsigned af[4][4], bf_[2][4];
#pragma unroll
            for (int mt = 0; mt < 4; mt++)
                ldsm_x4(af[mt], sptr(&As[buf][(wm + mt * 16 + a_m) * AST + ks * 16 + a_k]));
#pragma unroll
            for (int ng = 0; ng < 2; ng++)
                ldsm_x4t(bf_[ng], sptr(&Bs[buf][(ks * 16 + b_k) * BST + wn + ng * 16 + b_n]));
#pragma unroll
            for (int mt = 0; mt < 4; mt++)
#pragma unroll
                for (int nt = 0; nt < 4; nt++)
                    mma_bf16(acc[mt][nt], af[mt], &bf_[nt >> 1][(nt & 1) * 2], acc[mt][nt]);
        }
        __syncthreads();
    }

    // Epilogue
#pragma unroll
    for (int mt = 0; mt < 4; mt++) {
        int mA = m0 + wm + mt * 16 + r0;
        float f0 = 1.f, f1 = 1.f;
        if (qscale) {
            f0 = ((mA % 192) < 64) ? SCALE : 1.f;
            f1 = (((mA + 8) % 192) < 64) ? SCALE : 1.f;
        }
#pragma unroll
        for (int nt = 0; nt < 4; nt++) {
            int n = n0 + wn + nt * 8 + 2 * c2;
            if (Cb) {
                bf16 p0[2] = {tob(acc[mt][nt][0] * f0), tob(acc[mt][nt][1] * f0)};
                bf16 p1[2] = {tob(acc[mt][nt][2] * f1), tob(acc[mt][nt][3] * f1)};
                *(unsigned*)(Cb + (size_t)mA * N + n) = *(unsigned*)p0;
                *(unsigned*)(Cb + (size_t)(mA + 8) * N + n) = *(unsigned*)p1;
            } else {
                float bv0 = bias[mA], bv1 = bias[mA + 8];
                float2 o0, o1;
                o0.x = acc[mt][nt][0] + bv0; o0.y = acc[mt][nt][1] + bv0;
                o1.x = acc[mt][nt][2] + bv1; o1.y = acc[mt][nt][3] + bv1;
                float2 q0v = *(const float2*)(res + (size_t)mA * N + n);
                float2 q1v = *(const float2*)(res + (size_t)(mA + 8) * N + n);
                o0.x += q0v.x; o0.y += q0v.y; o1.x += q1v.x; o1.y += q1v.y;
                *(float2*)(Cf + (size_t)mA * N + n) = o0;
                *(float2*)(Cf + (size_t)(mA + 8) * N + n) = o1;
            }
        }
    }
}

__global__ void __launch_bounds__(256, 2) qkv_gemm_kernel() {
    int b = blockIdx.z;
    gemm_core(3 * CCH, SSP, CCH, g_wqb,
              g_norm + (size_t)b * CCH * SSP,
              g_qkv + (size_t)b * 3 * CCH * SSP, nullptr,
              nullptr, nullptr, true);
}

__global__ void __launch_bounds__(256, 2) out_gemm_kernel(const float* __restrict__ b_out,
                                                          const float* __restrict__ x,
                                                          float* __restrict__ out) {
    int b = blockIdx.z;
    gemm_core(CCH, SSP, CCH, g_wob,
              g_att + (size_t)b * CCH * SSP,
              nullptr, out + (size_t)b * CCH * SSP,
              b_out, x + (size_t)b * CCH * SSP, false);
}

// ---------------------------------------------------------------------------
// Flash attention bf16. Block = 128 queries of one (b,h), 256 threads = 8
// warps, each warp 16 query rows x all 64 keys of the tile. K/V cp.async
// double-buffered. Q pre-scaled (folded in qkv epilogue).
// SMEM: Qs[64d][136i], Ks[2][64d][72j], Vs[2][64d][72j], Ps[128i][72j].
// ---------------------------------------------------------------------------
#define QST 136
#define KST 72
#define NT_TILES (SSP / 64)

__global__ void __launch_bounds__(256, 2) attn_kernel() {
    extern __shared__ bf16 smn[];
    bf16* Qs = smn;                       // 64*136
    bf16* Ks = Qs + 64 * QST;             // 2*64*72
    bf16* Vs = Ks + 2 * 64 * KST;         // 2*64*72
    bf16* Ps = Vs + 2 * 64 * KST;         // 128*72

    int tid = threadIdx.x, lane = tid & 31, w = tid >> 5;
    int r0 = lane >> 2, c2 = lane & 3;
    int wm = w * 16;
    int h = blockIdx.y, b = blockIdx.z;
    int q0 = blockIdx.x * 128;
    const bf16* qp = g_qkv + ((size_t)b * 3 * CCH + h * 3 * HD) * SSP;
    const bf16* kp = qp + (size_t)HD * SSP;
    const bf16* vp = qp + (size_t)2 * HD * SSP;

    // ldmatrix lane-address components
    int t8  = (lane >> 3) & 1, t16 = (lane >> 4) & 1, t7 = lane & 7;

    // Load Q tile [d][i] (plain 16B loads; already bf16 + scaled)
    {
        int io = (tid & 15) * 8, d = tid >> 4;
#pragma unroll
        for (int r = 0; r < 4; r++)
            *(uint4*)(Qs + (d + 16 * r) * QST + io) =
                *(const uint4*)(qp + (size_t)(d + 16 * r) * SSP + q0 + io);
    }

    // K/V loaders
    int ld = tid >> 3, ljo = (tid & 7) * 8;
    // preload tile 0
#pragma unroll
    for (int r = 0; r < 2; r++) {
        CP16(sptr(Ks + (ld + 32 * r) * KST + ljo), kp + (size_t)(ld + 32 * r) * SSP + ljo);
        CP16(sptr(Vs + (ld + 32 * r) * KST + ljo), vp + (size_t)(ld + 32 * r) * SSP + ljo);
    }
    CP_COMMIT();

    float m_run[2] = {-1e30f, -1e30f}, l_run[2] = {0.f, 0.f};
    float o[8][4];
#pragma unroll
    for (int nt = 0; nt < 8; nt++)
#pragma unroll
        for (int e = 0; e < 4; e++) o[nt][e] = 0.f;

    for (int t = 0; t < NT_TILES; t++) {
        int buf = t & 1;
        if (t + 1 < NT_TILES) {
            int nb = buf ^ 1;
            int t0n = (t + 1) * 64;
#pragma unroll
            for (int r = 0; r < 2; r++) {
                CP16(sptr(Ks + (nb * 64 + ld + 32 * r) * KST + ljo),
                     kp + (size_t)(ld + 32 * r) * SSP + t0n + ljo);
                CP16(sptr(Vs + (nb * 64 + ld + 32 * r) * KST + ljo),
                     vp + (size_t)(ld + 32 * r) * SSP + t0n + ljo);
            }
            CP_COMMIT();
            CP_WAIT1();
        } else {
            CP_WAIT0();
        }
        __syncthreads();

        // ---- S = Q^T K : A from Qs ([d][i], .trans), B from Ks ([d][j], .trans)
        float s[8][4];
#pragma unroll
        for (int nt = 0; nt < 8; nt++)
#pragma unroll
            for (int e = 0; e < 4; e++) s[nt][e] = 0.f;
        const bf16* Kb = Ks + buf * 64 * KST;
#pragma unroll
        for (int ks = 0; ks < 4; ks++) {
            unsigned a[4], bb[4][4];
            ldsm_x4t(a, sptr(Qs + (ks * 16 + t16 * 8 + t7) * QST + wm + t8 * 8));
#pragma unroll
            for (int ng = 0; ng < 4; ng++)
                ldsm_x4t(bb[ng], sptr(Kb + (ks * 16 + t8 * 8 + t7) * KST + ng * 16 + t16 * 8));
#pragma unroll
            for (int nt = 0; nt < 8; nt++)
                mma_bf16(s[nt], a, &bb[nt >> 1][(nt & 1) * 2], s[nt]);
        }

        // ---- online softmax (rows wm+r0 and wm+r0+8)
        float mx0 = -1e30f, mx1 = -1e30f;
#pragma unroll
        for (int nt = 0; nt < 8; nt++) {
            mx0 = fmaxf(mx0, fmaxf(s[nt][0], s[nt][1]));
            mx1 = fmaxf(mx1, fmaxf(s[nt][2], s[nt][3]));
        }
#pragma unroll
        for (int off = 1; off <= 2; off <<= 1) {
            mx0 = fmaxf(mx0, __shfl_xor_sync(0xffffffffu, mx0, off));
            mx1 = fmaxf(mx1, __shfl_xor_sync(0xffffffffu, mx1, off));
        }
        float mn0 = fmaxf(m_run[0], mx0), mn1 = fmaxf(m_run[1], mx1);
        float cr0 = __expf(m_run[0] - mn0), cr1 = __expf(m_run[1] - mn1);
        m_run[0] = mn0; m_run[1] = mn1;
        float sum0 = 0.f, sum1 = 0.f;
#pragma unroll
        for (int nt = 0; nt < 8; nt++) {
            s[nt][0] = __expf(s[nt][0] - mn0);
            s[nt][1] = __expf(s[nt][1] - mn0);
            s[nt][2] = __expf(s[nt][2] - mn1);
            s[nt][3] = __expf(s[nt][3] - mn1);
            sum0 += s[nt][0] + s[nt][1];
            sum1 += s[nt][2] + s[nt][3];
        }
#pragma unroll
        for (int off = 1; off <= 2; off <<= 1) {
            sum0 += __shfl_xor_sync(0xffffffffu, sum0, off);
            sum1 += __shfl_xor_sync(0xffffffffu, sum1, off);
        }
        l_run[0] = l_run[0] * cr0 + sum0;
        l_run[1] = l_run[1] * cr1 + sum1;
#pragma unroll
        for (int nt = 0; nt < 8; nt++) {
            o[nt][0] *= cr0; o[nt][1] *= cr0;
            o[nt][2] *= cr1; o[nt][3] *= cr1;
        }

        // ---- store P bf16 (own rows only)
#pragma unroll
        for (int nt = 0; nt < 8; nt++) {
            bf16 p0[2] = {tob(s[nt][0]), tob(s[nt][1])};
            bf16 p1[2] = {tob(s[nt][2]), tob(s[nt][3])};
            *(unsigned*)(Ps + (wm + r0) * KST + nt * 8 + 2 * c2) = *(unsigned*)p0;
            *(unsigned*)(Ps + (wm + r0 + 8) * KST + nt * 8 + 2 * c2) = *(unsigned*)p1;
        }
        __syncwarp();

        // ---- O += P V : A from Ps ([i][j], no-trans), B from Vs ([dd][j], no-trans)
        const bf16* Vb = Vs + buf * 64 * KST;
#pragma unroll
        for (int ks = 0; ks < 4; ks++) {
            unsigned a[4], bb[4][4];
            ldsm_x4(a, sptr(Ps + (wm + t8 * 8 + t7) * KST + ks * 16 + t16 * 8));
#pragma unroll
            for (int ng = 0; ng < 4; ng++)
                ldsm_x4(bb[ng], sptr(Vb + (ng * 16 + t16 * 8 + t7) * KST + ks * 16 + t8 * 8));
#pragma unroll
            for (int nt = 0; nt < 8; nt++)
                mma_bf16(o[nt], a, &bb[nt >> 1][(nt & 1) * 2], o[nt]);
        }
        __syncthreads();
    }

    // ---- finalize: stage [dd][i] into Qs, then coalesced bf16 writes
    float inv0 = 1.f / l_run[0], inv1 = 1.f / l_run[1];
    bf16* Os = Qs;  // reuse, 64 x 136
#pragma unroll
    for (int nt = 0; nt < 8; nt++) {
        int dd = nt * 8 + 2 * c2;
        Os[dd * QST + wm + r0]           = tob(o[nt][0] * inv0);
        Os[(dd + 1) * QST + wm + r0]     = tob(o[nt][1] * inv0);
        Os[dd * QST + wm + r0 + 8]       = tob(o[nt][2] * inv1);
        Os[(dd + 1) * QST + wm + r0 + 8] = tob(o[nt][3] * inv1);
    }
    __syncthreads();
    bf16* ap = g_att + ((size_t)b * CCH + h * HD) * SSP;
    {
        int io = (tid & 15) * 8, d = tid >> 4;
#pragma unroll
        for (int r = 0; r < 4; r++)
            *(uint4*)(ap + (size_t)(d + 16 * r) * SSP + q0 + io) =
                *(uint4*)(Os + (d + 16 * r) * QST + io);
    }
}

// ---------------------------------------------------------------------------
extern "C" void kernel_launch(void* const* d_in, const int* in_sizes, int n_in,
                              void* d_out, int out_size) {
    const float* x     = (const float*)d_in[0];
    const float* gamma = (const float*)d_in[1];
    const float* beta  = (const float*)d_in[2];
    const float* w_qkv = (const float*)d_in[3];
    const float* w_out = (const float*)d_in[4];
    const float* b_out = (const float*)d_in[5];
    float* out = (float*)d_out;

    const int attn_smem = (64 * QST + 4 * 64 * KST + 128 * KST) * (int)sizeof(bf16);
    cudaFuncSetAttribute(attn_kernel, cudaFuncAttributeMaxDynamicSharedMemorySize,
                         attn_smem);

    wconv_kernel<<<1024, 256>>>(w_qkv, w_out);
    gn_kernel<<<BATCH * 32, 256>>>(x, gamma, beta);
    qkv_gemm_kernel<<<dim3(SSP / 128, 3 * CCH / 128, BATCH), 256>>>();
    attn_kernel<<<dim3(SSP / 128, NH, BATCH), 256, attn_smem>>>();
    out_gemm_kernel<<<dim3(SSP / 128, CCH / 128, BATCH), 256>>>(b_out, x, out);
}

// round 5
// speedup vs baseline: 6.3092x; 1.0423x over previous
#include <cuda_runtime.h>
#include <cuda_bf16.h>
#include <cstdint>

#define BATCH 2
#define CCH   512
#define SSP   2304
#define NH    8
#define HD    64
#define CPG   16
#define EPSV  1e-5f
// softmax scale with log2(e) folded in: attention computed in log2 domain
#define QSC   (0.044194173824159216f * 1.4426950408889634f)

typedef __nv_bfloat16 bf16;

// Scratch (allocation-free rule: __device__ globals) — bf16 intermediates
__device__ bf16 g_norm[BATCH * CCH * SSP];
__device__ bf16 g_qkv [BATCH * 3 * CCH * SSP];
__device__ bf16 g_att [BATCH * CCH * SSP];
__device__ bf16 g_wqb [3 * CCH * CCH];
__device__ bf16 g_wob [CCH * CCH];

// ---------------------------------------------------------------------------
// PTX helpers
// ---------------------------------------------------------------------------
__device__ __forceinline__ unsigned sptr(const void* p) {
    return (unsigned)__cvta_generic_to_shared(p);
}
__device__ __forceinline__ void ldsm_x4(unsigned r[4], unsigned a) {
    asm volatile("ldmatrix.sync.aligned.m8n8.x4.shared.b16 {%0,%1,%2,%3}, [%4];"
                 : "=r"(r[0]), "=r"(r[1]), "=r"(r[2]), "=r"(r[3]) : "r"(a));
}
__device__ __forceinline__ void ldsm_x4t(unsigned r[4], unsigned a) {
    asm volatile("ldmatrix.sync.aligned.m8n8.x4.trans.shared.b16 {%0,%1,%2,%3}, [%4];"
                 : "=r"(r[0]), "=r"(r[1]), "=r"(r[2]), "=r"(r[3]) : "r"(a));
}
__device__ __forceinline__ void mma_bf16(float d[4], const unsigned a[4],
                                         const unsigned b[2], const float c[4]) {
    asm volatile(
        "mma.sync.aligned.m16n8k16.row.col.f32.bf16.bf16.f32 "
        "{%0,%1,%2,%3}, {%4,%5,%6,%7}, {%8,%9}, {%10,%11,%12,%13};\n"
        : "=f"(d[0]), "=f"(d[1]), "=f"(d[2]), "=f"(d[3])
        : "r"(a[0]), "r"(a[1]), "r"(a[2]), "r"(a[3]), "r"(b[0]), "r"(b[1]),
          "f"(c[0]), "f"(c[1]), "f"(c[2]), "f"(c[3]));
}
__device__ __forceinline__ float ex2(float x) {
    float y;
    asm("ex2.approx.f32 %0, %1;" : "=f"(y) : "f"(x));
    return y;
}
#define CP16(dst, src) \
    asm volatile("cp.async.cg.shared.global [%0], [%1], 16;" :: "r"(dst), "l"(src) : "memory")
#define CP_COMMIT() asm volatile("cp.async.commit_group;" ::: "memory")
#define CP_WAIT1()  asm volatile("cp.async.wait_group 1;" ::: "memory")
#define CP_WAIT0()  asm volatile("cp.async.wait_group 0;" ::: "memory")

__device__ __forceinline__ bf16 tob(float f) { return __float2bfloat16_rn(f); }

// ---------------------------------------------------------------------------
// Weight conversion fp32 -> bf16
// ---------------------------------------------------------------------------
__global__ void wconv_kernel(const float* __restrict__ wq,
                             const float* __restrict__ wo) {
    int t = blockIdx.x * 256 + threadIdx.x;
    const int n1 = 3 * CCH * CCH / 4;
    const int n2 = CCH * CCH / 4;
    if (t < n1) {
        float4 v = ((const float4*)wq)[t];
        bf16* o = g_wqb + t * 4;
        o[0] = tob(v.x); o[1] = tob(v.y); o[2] = tob(v.z); o[3] = tob(v.w);
    } else if (t < n1 + n2) {
        int u = t - n1;
        float4 v = ((const float4*)wo)[u];
        bf16* o = g_wob + u * 4;
        o[0] = tob(v.x); o[1] = tob(v.y); o[2] = tob(v.z); o[3] = tob(v.w);
    }
}

// ---------------------------------------------------------------------------
// GroupNorm -> bf16
// ---------------------------------------------------------------------------
__global__ void gn_kernel(const float* __restrict__ x,
                          const float* __restrict__ gamma,
                          const float* __restrict__ beta) {
    int b = blockIdx.x >> 5;
    int g = blockIdx.x & 31;
    const float4* xp = (const float4*)(x + (size_t)(b * CCH + g * CPG) * SSP);
    bf16* op = g_norm + (size_t)(b * CCH + g * CPG) * SSP;
    int tid = threadIdx.x;
    const int n4 = CPG * SSP / 4;  // 9216

    float s0 = 0.f, s1 = 0.f;
    for (int i = tid; i < n4; i += 256) {
        float4 v = xp[i];
        s0 += v.x + v.y + v.z + v.w;
        s1 += v.x * v.x + v.y * v.y + v.z * v.z + v.w * v.w;
    }
#pragma unroll
    for (int o = 16; o > 0; o >>= 1) {
        s0 += __shfl_xor_sync(0xffffffffu, s0, o);
        s1 += __shfl_xor_sync(0xffffffffu, s1, o);
    }
    __shared__ float sm0[8], sm1[8], stat[2];
    int w = tid >> 5;
    if ((tid & 31) == 0) { sm0[w] = s0; sm1[w] = s1; }
    __syncthreads();
    if (tid == 0) {
        float a = 0.f, q = 0.f;
#pragma unroll
        for (int i = 0; i < 8; i++) { a += sm0[i]; q += sm1[i]; }
        float mean = a * (1.f / 36864.f);
        float var  = q * (1.f / 36864.f) - mean * mean;
        stat[0] = mean;
        stat[1] = rsqrtf(var + EPSV);
    }
    __syncthreads();
    float mean = stat[0], rstd = stat[1];
    for (int i = tid; i < n4; i += 256) {
        int c = g * CPG + i / 576;
        float ga = gamma[c] * rstd;
        float be = beta[c] - mean * ga;
        float4 v = xp[i];
        bf16 o4[4];
        o4[0] = tob(v.x * ga + be); o4[1] = tob(v.y * ga + be);
        o4[2] = tob(v.z * ga + be); o4[3] = tob(v.w * ga + be);
        *(uint2*)(op + i * 4) = *(uint2*)o4;
    }
}

// ---------------------------------------------------------------------------
// bf16 tensor-core GEMM: C[M,N] = A[M,K] @ B[K,N]. 128x128 tile, ktile 32,
// 256 thr = 8 warps (2Mx4N), warp 64x32. cp.async 2-stage double buffer.
// qscale: rows with (m%192)<64 scaled by QSC (Q rows; folds softmax scale
// and log2e into Q).
// ---------------------------------------------------------------------------
#define AST 40
#define BST 136

__device__ __forceinline__ void gemm_core(
    int M, int N, int K,
    const bf16* __restrict__ A, const bf16* __restrict__ Bp,
    bf16* __restrict__ Cb, float* __restrict__ Cf,
    const float* __restrict__ bias, const float* __restrict__ res,
    bool qscale) {
    __shared__ bf16 As[2][128 * AST];
    __shared__ bf16 Bs[2][32 * BST];
    int tid = threadIdx.x;
    int lane = tid & 31, wid = tid >> 5;
    int wm = (wid >> 2) * 64, wn = (wid & 3) * 32;
    int m0 = blockIdx.y * 128, n0 = blockIdx.x * 128;
    int r0 = lane >> 2, c2 = lane & 3;

    int lm = tid >> 2, lko = (tid & 3) * 8;
    int lk = tid >> 4, lno = (tid & 15) * 8;

    const bf16* Ag = A + (size_t)(m0 + lm) * K + lko;
    const bf16* Bg = Bp + (size_t)lk * N + n0 + lno;

    int a_m = ((lane >> 3) & 1) * 8 + (lane & 7);
    int a_k = ((lane >> 4) & 1) * 8;
    int b_k = ((lane >> 3) & 1) * 8 + (lane & 7);
    int b_n = ((lane >> 4) & 1) * 8;

    float acc[4][4][4];
#pragma unroll
    for (int mt = 0; mt < 4; mt++)
#pragma unroll
        for (int nt = 0; nt < 4; nt++)
#pragma unroll
            for (int e = 0; e < 4; e++) acc[mt][nt][e] = 0.f;

    int nkt = K >> 5;
#pragma unroll
    for (int r = 0; r < 2; r++) {
        CP16(sptr(&As[0][(lm + r * 64) * AST + lko]), Ag + (size_t)r * 64 * K);
        CP16(sptr(&Bs[0][(lk + r * 16) * BST + lno]), Bg + (size_t)r * 16 * N);
    }
    CP_COMMIT();

    for (int kt = 0; kt < nkt; kt++) {
        int buf = kt & 1;
        if (kt + 1 < nkt) {
            int nb = buf ^ 1;
#pragma unroll
            for (int r = 0; r < 2; r++) {
                CP16(sptr(&As[nb][(lm + r * 64) * AST + lko]),
                     Ag + (size_t)(kt + 1) * 32 + (size_t)r * 64 * K);
                CP16(sptr(&Bs[nb][(lk + r * 16) * BST + lno]),
                     Bg + (size_t)((kt + 1) * 32 + r * 16) * N);
            }
            CP_COMMIT();
            CP_WAIT1();
        } else {
            CP_WAIT0();
        }
        __syncthreads();

#pragma unroll
        for (int ks = 0; ks < 2; ks++) {
            unsigned af[4][4], bf_[2][4];
#pragma unroll
            for (int mt = 0; mt < 4; mt++)
                ldsm_x4(af[mt], sptr(&As[buf][(wm + mt * 16 + a_m) * AST + ks * 16 + a_k]));
#pragma unroll
            for (int ng = 0; ng < 2; ng++)
                ldsm_x4t(bf_[ng], sptr(&Bs[buf][(ks * 16 + b_k) * BST + wn + ng * 16 + b_n]));
#pragma unroll
            for (int mt = 0; mt < 4; mt++)
#pragma unroll
                for (int nt = 0; nt < 4; nt++)
                    mma_bf16(acc[mt][nt], af[mt], &bf_[nt >> 1][(nt & 1) * 2], acc[mt][nt]);
        }
        __syncthreads();
    }

#pragma unroll
    for (int mt = 0; mt < 4; mt++) {
        int mA = m0 + wm + mt * 16 + r0;
        float f0 = 1.f, f1 = 1.f;
        if (qscale) {
            f0 = ((mA % 192) < 64) ? QSC : 1.f;
            f1 = (((mA + 8) % 192) < 64) ? QSC : 1.f;
        }
#pragma unroll
        for (int nt = 0; nt < 4; nt++) {
            int n = n0 + wn + nt * 8 + 2 * c2;
            if (Cb) {
                bf16 p0[2] = {tob(acc[mt][nt][0] * f0), tob(acc[mt][nt][1] * f0)};
                bf16 p1[2] = {tob(acc[mt][nt][2] * f1), tob(acc[mt][nt][3] * f1)};
                *(unsigned*)(Cb + (size_t)mA * N + n) = *(unsigned*)p0;
                *(unsigned*)(Cb + (size_t)(mA + 8) * N + n) = *(unsigned*)p1;
            } else {
                float bv0 = bias[mA], bv1 = bias[mA + 8];
                float2 o0, o1;
                o0.x = acc[mt][nt][0] + bv0; o0.y = acc[mt][nt][1] + bv0;
                o1.x = acc[mt][nt][2] + bv1; o1.y = acc[mt][nt][3] + bv1;
                float2 q0v = *(const float2*)(res + (size_t)mA * N + n);
                float2 q1v = *(const float2*)(res + (size_t)(mA + 8) * N + n);
                o0.x += q0v.x; o0.y += q0v.y; o1.x += q1v.x; o1.y += q1v.y;
                *(float2*)(Cf + (size_t)mA * N + n) = o0;
                *(float2*)(Cf + (size_t)(mA + 8) * N + n) = o1;
            }
        }
    }
}

__global__ void __launch_bounds__(256, 2) qkv_gemm_kernel() {
    int b = blockIdx.z;
    gemm_core(3 * CCH, SSP, CCH, g_wqb,
              g_norm + (size_t)b * CCH * SSP,
              g_qkv + (size_t)b * 3 * CCH * SSP, nullptr,
              nullptr, nullptr, true);
}

__global__ void __launch_bounds__(256, 2) out_gemm_kernel(const float* __restrict__ b_out,
                                                          const float* __restrict__ x,
                                                          float* __restrict__ out) {
    int b = blockIdx.z;
    gemm_core(CCH, SSP, CCH, g_wob,
              g_att + (size_t)b * CCH * SSP,
              nullptr, out + (size_t)b * CCH * SSP,
              b_out, x + (size_t)b * CCH * SSP, false);
}

// ---------------------------------------------------------------------------
// Flash attention bf16, log2-domain softmax, interleaved exp/PV.
// Block = 128 queries of one (b,h), 256 threads = 8 warps. K/V cp.async
// double-buffered. Q pre-scaled by QSC (folded in qkv epilogue).
// ---------------------------------------------------------------------------
#define QST 136
#define KST 72
#define NT_TILES (SSP / 64)

__global__ void __launch_bounds__(256, 2) attn_kernel() {
    extern __shared__ bf16 smn[];
    bf16* Qs = smn;                       // 64*136
    bf16* Ks = Qs + 64 * QST;             // 2*64*72
    bf16* Vs = Ks + 2 * 64 * KST;         // 2*64*72
    bf16* Ps = Vs + 2 * 64 * KST;         // 128*72

    int tid = threadIdx.x, lane = tid & 31, w = tid >> 5;
    int r0 = lane >> 2, c2 = lane & 3;
    int wm = w * 16;
    int h = blockIdx.y, b = blockIdx.z;
    int q0 = blockIdx.x * 128;
    const bf16* qp = g_qkv + ((size_t)b * 3 * CCH + h * 3 * HD) * SSP;
    const bf16* kp = qp + (size_t)HD * SSP;
    const bf16* vp = qp + (size_t)2 * HD * SSP;

    int t8  = (lane >> 3) & 1, t16 = (lane >> 4) & 1, t7 = lane & 7;

    // Load Q tile [d][i]
    {
        int io = (tid & 15) * 8, d = tid >> 4;
#pragma unroll
        for (int r = 0; r < 4; r++)
            *(uint4*)(Qs + (d + 16 * r) * QST + io) =
                *(const uint4*)(qp + (size_t)(d + 16 * r) * SSP + q0 + io);
    }

    int ld = tid >> 3, ljo = (tid & 7) * 8;
#pragma unroll
    for (int r = 0; r < 2; r++) {
        CP16(sptr(Ks + (ld + 32 * r) * KST + ljo), kp + (size_t)(ld + 32 * r) * SSP + ljo);
        CP16(sptr(Vs + (ld + 32 * r) * KST + ljo), vp + (size_t)(ld + 32 * r) * SSP + ljo);
    }
    CP_COMMIT();

    float m_run[2] = {-1e30f, -1e30f}, l_run[2] = {0.f, 0.f};
    float o[8][4];
#pragma unroll
    for (int nt = 0; nt < 8; nt++)
#pragma unroll
        for (int e = 0; e < 4; e++) o[nt][e] = 0.f;

    for (int t = 0; t < NT_TILES; t++) {
        int buf = t & 1;
        if (t + 1 < NT_TILES) {
            int nb = buf ^ 1;
            int t0n = (t + 1) * 64;
#pragma unroll
            for (int r = 0; r < 2; r++) {
                CP16(sptr(Ks + (nb * 64 + ld + 32 * r) * KST + ljo),
                     kp + (size_t)(ld + 32 * r) * SSP + t0n + ljo);
                CP16(sptr(Vs + (nb * 64 + ld + 32 * r) * KST + ljo),
                     vp + (size_t)(ld + 32 * r) * SSP + t0n + ljo);
            }
            CP_COMMIT();
            CP_WAIT1();
        } else {
            CP_WAIT0();
        }
        __syncthreads();

        // ---- S = Q^T K (log2-domain scores)
        float s[8][4];
#pragma unroll
        for (int nt = 0; nt < 8; nt++)
#pragma unroll
            for (int e = 0; e < 4; e++) s[nt][e] = 0.f;
        const bf16* Kb = Ks + buf * 64 * KST;
#pragma unroll
        for (int ks = 0; ks < 4; ks++) {
            unsigned a[4], bb[4][4];
            ldsm_x4t(a, sptr(Qs + (ks * 16 + t16 * 8 + t7) * QST + wm + t8 * 8));
#pragma unroll
            for (int ng = 0; ng < 4; ng++)
                ldsm_x4t(bb[ng], sptr(Kb + (ks * 16 + t8 * 8 + t7) * KST + ng * 16 + t16 * 8));
#pragma unroll
            for (int nt = 0; nt < 8; nt++)
                mma_bf16(s[nt], a, &bb[nt >> 1][(nt & 1) * 2], s[nt]);
        }

        // ---- row max (quad reduction)
        float mx0 = -1e30f, mx1 = -1e30f;
#pragma unroll
        for (int nt = 0; nt < 8; nt++) {
            mx0 = fmaxf(mx0, fmaxf(s[nt][0], s[nt][1]));
            mx1 = fmaxf(mx1, fmaxf(s[nt][2], s[nt][3]));
        }
#pragma unroll
        for (int off = 1; off <= 2; off <<= 1) {
            mx0 = fmaxf(mx0, __shfl_xor_sync(0xffffffffu, mx0, off));
            mx1 = fmaxf(mx1, __shfl_xor_sync(0xffffffffu, mx1, off));
        }
        float mn0 = fmaxf(m_run[0], mx0), mn1 = fmaxf(m_run[1], mx1);
        float cr0 = ex2(m_run[0] - mn0), cr1 = ex2(m_run[1] - mn1);
        m_run[0] = mn0; m_run[1] = mn1;
#pragma unroll
        for (int nt = 0; nt < 8; nt++) {
            o[nt][0] *= cr0; o[nt][1] *= cr0;
            o[nt][2] *= cr1; o[nt][3] *= cr1;
        }

        // ---- interleaved: exp2 chunk of P, then PV mma for that k-chunk
        float sum0 = 0.f, sum1 = 0.f;
        const bf16* Vb = Vs + buf * 64 * KST;
#pragma unroll
        for (int ks = 0; ks < 4; ks++) {
#pragma unroll
            for (int u = 0; u < 2; u++) {
                int nt = ks * 2 + u;
                s[nt][0] = ex2(s[nt][0] - mn0);
                s[nt][1] = ex2(s[nt][1] - mn0);
                s[nt][2] = ex2(s[nt][2] - mn1);
                s[nt][3] = ex2(s[nt][3] - mn1);
                sum0 += s[nt][0] + s[nt][1];
                sum1 += s[nt][2] + s[nt][3];
                bf16 p0[2] = {tob(s[nt][0]), tob(s[nt][1])};
                bf16 p1[2] = {tob(s[nt][2]), tob(s[nt][3])};
                *(unsigned*)(Ps + (wm + r0) * KST + nt * 8 + 2 * c2) = *(unsigned*)p0;
                *(unsigned*)(Ps + (wm + r0 + 8) * KST + nt * 8 + 2 * c2) = *(unsigned*)p1;
            }
            __syncwarp();
            unsigned a[4], bb[4][4];
            ldsm_x4(a, sptr(Ps + (wm + t8 * 8 + t7) * KST + ks * 16 + t16 * 8));
#pragma unroll
            for (int ng = 0; ng < 4; ng++)
                ldsm_x4(bb[ng], sptr(Vb + (ng * 16 + t16 * 8 + t7) * KST + ks * 16 + t8 * 8));
#pragma unroll
            for (int nd = 0; nd < 8; nd++)
                mma_bf16(o[nd], a, &bb[nd >> 1][(nd & 1) * 2], o[nd]);
        }

#pragma unroll
        for (int off = 1; off <= 2; off <<= 1) {
            sum0 += __shfl_xor_sync(0xffffffffu, sum0, off);
            sum1 += __shfl_xor_sync(0xffffffffu, sum1, off);
        }
        l_run[0] = l_run[0] * cr0 + sum0;
        l_run[1] = l_run[1] * cr1 + sum1;
        __syncthreads();
    }

    // ---- finalize
    float inv0 = 1.f / l_run[0], inv1 = 1.f / l_run[1];
    bf16* Os = Qs;
#pragma unroll
    for (int nt = 0; nt < 8; nt++) {
        int dd = nt * 8 + 2 * c2;
        Os[dd * QST + wm + r0]           = tob(o[nt][0] * inv0);
        Os[(dd + 1) * QST + wm + r0]     = tob(o[nt][1] * inv0);
        Os[dd * QST + wm + r0 + 8]       = tob(o[nt][2] * inv1);
        Os[(dd + 1) * QST + wm + r0 + 8] = tob(o[nt][3] * inv1);
    }
    __syncthreads();
    bf16* ap = g_att + ((size_t)b * CCH + h * HD) * SSP;
    {
        int io = (tid & 15) * 8, d = tid >> 4;
#pragma unroll
        for (int r = 0; r < 4; r++)
            *(uint4*)(ap + (size_t)(d + 16 * r) * SSP + q0 + io) =
                *(uint4*)(Os + (d + 16 * r) * QST + io);
    }
}

// ---------------------------------------------------------------------------
extern "C" void kernel_launch(void* const* d_in, const int* in_sizes, int n_in,
                              void* d_out, int out_size) {
    const float* x     = (const float*)d_in[0];
    const float* gamma = (const float*)d_in[1];
    const float* beta  = (const float*)d_in[2];
    const float* w_qkv = (const float*)d_in[3];
    const float* w_out = (const float*)d_in[4];
    const float* b_out = (const float*)d_in[5];
    float* out = (float*)d_out;

    const int attn_smem = (64 * QST + 4 * 64 * KST + 128 * KST) * (int)sizeof(bf16);
    cudaFuncSetAttribute(attn_kernel, cudaFuncAttributeMaxDynamicSharedMemorySize,
                         attn_smem);

    wconv_kernel<<<1024, 256>>>(w_qkv, w_out);
    gn_kernel<<<BATCH * 32, 256>>>(x, gamma, beta);
    qkv_gemm_kernel<<<dim3(SSP / 128, 3 * CCH / 128, BATCH), 256>>>();
    attn_kernel<<<dim3(SSP / 128, NH, BATCH), 256, attn_smem>>>();
    out_gemm_kernel<<<dim3(SSP / 128, CCH / 128, BATCH), 256>>>(b_out, x, out);
}